// round 11
// baseline (speedup 1.0000x reference)
#include <cuda_runtime.h>
#include <cstdint>

#define BB   8
#define CC   128
#define HWD  4096
#define LL   4096
#define DMI  32
#define DII  64
#define DSS  64
#define NCHK 32
#define BL   (BB*LL)   // 32768

// ---------------- scratch (device globals) ----------------
__device__ float g_t1[BB*CC*HWD];
__device__ float g_o1[BB*CC*HWD];
__device__ float g_s[BL*DMI];
__device__ float g_z[2][BL*DII];
__device__ float g_xbcT[2][192*BL];     // post conv+silu, [ch][row]; ch: 0..63 xs, 64..127 B, 128..191 C
__device__ float g_dt[2][BL];
__device__ float g_cd[2][BL];
__device__ float g_S[2][BB*NCHK*DII*DSS];
__device__ float g_Hin[2][BB*NCHK*DII*DSS];
__device__ float g_yg[2][BL*DII];
__device__ float g_o2[BB*CC*HWD];
__device__ float g_bnA[CC], g_bnT[CC];
__device__ float g_W4[CC*CC], g_b4[CC];
__device__ float g_Wcomb[CC*CC];

__device__ __forceinline__ float sigf(float v){ return 1.f/(1.f+__expf(-v)); }

// ---------------- 1) lin1: per-pixel 128->128 GEMM + bias (64-out x 128-l tiles) ----------------
__global__ void __launch_bounds__(256) k_lin1(const float* __restrict__ x,
                       const float* __restrict__ W, const float* __restrict__ bias) {
    extern __shared__ float sm[];
    float* Wsm = sm;            // [128 i][64 o]
    float* xsm = sm + 8192;     // [128 ch][128 l]
    int lt = blockIdx.x, ot = blockIdx.y, b = blockIdx.z;
    int l0 = lt << 7; int o0 = ot << 6;
    const float* sb = x + (size_t)b*CC*HWD;
    for (int i = threadIdx.x; i < 8192; i += 256) {
        int ii = i >> 6, oo = i & 63;
        Wsm[i] = W[ii*128 + o0 + oo];
    }
    for (int i = threadIdx.x; i < 16384; i += 256) {
        int ch = i >> 7, l = i & 127;
        xsm[i] = sb[ch*HWD + l0 + l];
    }
    __syncthreads();
    int og = threadIdx.x & 15;    // 4 outs each
    int lg = threadIdx.x >> 4;    // 8 ls each
    float acc[4][8];
    #pragma unroll
    for (int a=0;a<4;a++)
        #pragma unroll
        for (int c2=0;c2<8;c2++) acc[a][c2]=0.f;
    for (int i=0;i<128;i++){
        float4 w0 = *(const float4*)&Wsm[i*64 + og*4];
        float4 x0 = *(const float4*)&xsm[i*128 + lg*8];
        float4 x1 = *(const float4*)&xsm[i*128 + lg*8 + 4];
        float wv[4] = {w0.x,w0.y,w0.z,w0.w};
        float xv[8] = {x0.x,x0.y,x0.z,x0.w,x1.x,x1.y,x1.z,x1.w};
        #pragma unroll
        for (int a=0;a<4;a++)
            #pragma unroll
            for (int c2=0;c2<8;c2++) acc[a][c2] += wv[a]*xv[c2];
    }
    #pragma unroll
    for (int a=0;a<4;a++){
        int o = o0 + og*4 + a; float bv = bias[o];
        float* dp = &g_t1[((size_t)b*CC + o)*HWD + l0 + lg*8];
        #pragma unroll
        for (int c2=0;c2<8;c2++) dp[c2] = acc[a][c2] + bv;
    }
}

// ---------------- 2) 3x3 depthwise conv + bias + silu ----------------
__global__ void k_dw(const float* __restrict__ wdw, const float* __restrict__ bdw) {
    int idx = blockIdx.x*256 + threadIdx.x;
    int l = idx & 4095; int bc = idx >> 12; int c = bc & 127;
    int hh = l >> 6; int ww = l & 63;
    const float* src = g_t1 + (size_t)bc*HWD;
    const float* wp = wdw + c*9;
    float acc = bdw[c];
    #pragma unroll
    for (int dy=-1; dy<=1; dy++){
        int y = hh+dy;
        if ((unsigned)y < 64u) {
            #pragma unroll
            for (int dx=-1; dx<=1; dx++){
                int x2 = ww+dx;
                if ((unsigned)x2 < 64u)
                    acc += src[y*64+x2] * wp[(dy+1)*3 + (dx+1)];
            }
        }
    }
    g_o1[idx] = acc * sigf(acc);
}

// ---------------- 3) fc_in: (b,l) 128->32 ----------------
__global__ void k_fcin(const float* __restrict__ Wfc) {
    extern __shared__ float sm[];
    float* xsm = sm;          // 128ch x 128l
    float* Wsm = sm + 16384;  // 128x32
    int b = blockIdx.y; int l0 = blockIdx.x << 7;
    for (int i = threadIdx.x; i < 16384; i += 256){
        int ch = i>>7, l = i&127;
        xsm[i] = g_o1[((size_t)b*CC+ch)*HWD + l0 + l];
    }
    for (int i = threadIdx.x; i < 4096; i += 256) Wsm[i] = Wfc[i];
    __syncthreads();
    int tl = (threadIdx.x & 31)*4;
    int td = (threadIdx.x >> 5)*4;
    float acc[4][4];
    #pragma unroll
    for (int i=0;i<4;i++)
        #pragma unroll
        for (int j=0;j<4;j++) acc[i][j]=0.f;
    for (int c2=0;c2<128;c2++){
        float4 xv = *(const float4*)&xsm[c2*128 + tl];
        float4 wv = *(const float4*)&Wsm[c2*32 + td];
        float xa[4] = {xv.x,xv.y,xv.z,xv.w};
        float wa[4] = {wv.x,wv.y,wv.z,wv.w};
        #pragma unroll
        for (int i=0;i<4;i++)
            #pragma unroll
            for (int j=0;j<4;j++) acc[i][j] += xa[i]*wa[j];
    }
    #pragma unroll
    for (int i=0;i<4;i++){
        float4 o4 = make_float4(acc[i][0],acc[i][1],acc[i][2],acc[i][3]);
        *(float4*)&g_s[(size_t)((b<<12) + l0 + tl + i)*32 + td] = o4;
    }
}

// ---------------- 4) fused in-projection GEMM (64 rows/block) + causal conv1d + silu ----------------
// smem float offsets:
#define SI_W   0        // [32][256]   8192
#define SI_ST  8192     // [32][72]    2304
#define SI_CW  10496    // 768
#define SI_CB  11264    // 192
#define SI_HAL 11456    // [192][3]    576
#define SI_XB  12032    // [64][73]    4672   (idx = ch'*73 + 4 + rowi; halo at +1..+3)
#define SI_TOT 16704
__global__ void __launch_bounds__(256) k_inproj(const float* __restrict__ Win,
        const float* __restrict__ cw, const float* __restrict__ cb) {
    extern __shared__ float sm[];
    int r = blockIdx.y; int row0 = blockIdx.x << 6;
    int b = row0 >> 12; int l0 = row0 & 4095;
    int tid = threadIdx.x;
    const float* Wr = Win + r*8224;
    for (int i = tid; i < 8192; i += 256) {
        int k = i >> 8, o = i & 255;
        sm[SI_W + i] = Wr[k*257 + o];
    }
    for (int i = tid; i < 2048; i += 256) {
        int row = i >> 5, k = i & 31;
        int l = l0 + row;
        int lsel = r ? (4095 - l) : l;
        sm[SI_ST + k*72 + row] = g_s[(size_t)((b<<12)+lsel)*32 + k];
    }
    for (int i = tid; i < 768; i += 256) sm[SI_CW + i] = cw[r*768 + i];
    if (tid < 192) sm[SI_CB + tid] = cb[r*192 + tid];
    __syncthreads();

    int tr = tid >> 5;   // 0..7 -> rows tr*8..+7 (of 64)
    int tc = tid & 31;   // cols tc + 32*j
    float acc[8][8];
    #pragma unroll
    for (int i=0;i<8;i++)
        #pragma unroll
        for (int j=0;j<8;j++) acc[i][j]=0.f;
    for (int k=0;k<32;k++){
        float4 a0 = *(const float4*)&sm[SI_ST + k*72 + tr*8];
        float4 a1 = *(const float4*)&sm[SI_ST + k*72 + tr*8 + 4];
        float av[8] = {a0.x,a0.y,a0.z,a0.w,a1.x,a1.y,a1.z,a1.w};
        float bv[8];
        #pragma unroll
        for (int j=0;j<8;j++) bv[j] = sm[SI_W + k*256 + tc + 32*j];
        #pragma unroll
        for (int i=0;i<8;i++)
            #pragma unroll
            for (int j=0;j<8;j++) acc[i][j] += av[i]*bv[j];
    }
    // z (j=0,1) -> global
    #pragma unroll
    for (int i=0;i<8;i++){
        int grow = row0 + tr*8 + i;
        g_z[r][(size_t)grow*64 + tc]      = acc[i][0];
        g_z[r][(size_t)grow*64 + tc + 32] = acc[i][1];
    }
    // halo rows l0-3..l0-1 for all 192 channels (recompute from g_s; zero at start)
    for (int i = tid; i < 576; i += 256) {
        int h = i / 192; int ch = i - h*192;
        int l = l0 - 3 + h;
        float v = 0.f;
        if (l >= 0) {
            int lsel = r ? (4095 - l) : l;
            const float* srow = &g_s[(size_t)((b<<12)+lsel)*32];
            #pragma unroll
            for (int k=0;k<32;k++) v += srow[k]*sm[SI_W + k*256 + 64 + ch];
        }
        sm[SI_HAL + ch*3 + h] = v;
    }
    __syncthreads();

    // three passes of 64 channels: stage -> conv+silu -> store
    #pragma unroll
    for (int p=0;p<3;p++){
        for (int i = tid; i < 192; i += 256) {
            int ch2 = i/3; int h = i - ch2*3;
            sm[SI_XB + ch2*73 + 1 + h] = sm[SI_HAL + (64*p + ch2)*3 + h];
        }
        int j0 = 2 + 2*p;
        #pragma unroll
        for (int i=0;i<8;i++){
            sm[SI_XB + tc*73      + 4 + tr*8 + i] = acc[i][j0];
            sm[SI_XB + (32+tc)*73 + 4 + tr*8 + i] = acc[i][j0+1];
        }
        __syncthreads();
        for (int i = tid; i < 4096; i += 256) {
            int ch2 = i >> 6; int rowi = i & 63;
            const float* xp = &sm[SI_XB + ch2*73 + 4 + rowi];
            int chg = 64*p + ch2;
            const float* w = &sm[SI_CW + chg*4];
            float a = sm[SI_CB + chg] + xp[-3]*w[0] + xp[-2]*w[1] + xp[-1]*w[2] + xp[0]*w[3];
            g_xbcT[r][(size_t)chg*BL + row0 + rowi] = a * sigf(a);
        }
        __syncthreads();
    }
}

// ---------------- 6) dt: in-proj dot + softplus + in-chunk cumsum ----------------
__global__ void k_dtscan(const float* __restrict__ dtb, const float* __restrict__ Win) {
    __shared__ float wc[32];
    __shared__ float wsum[4];
    int r = blockIdx.z, b = blockIdx.y, ch = blockIdx.x;
    int t = threadIdx.x;  // 128 threads
    if (t < 32) wc[t] = Win[r*8224 + t*257 + 256];
    __syncthreads();
    int l = ch*128 + t;
    int lsel = r ? (4095 - l) : l;
    const float* srow = &g_s[(size_t)((b<<12)+lsel)*32];
    float raw = dtb[r];
    #pragma unroll
    for (int k=0;k<32;k++) raw += srow[k]*wc[k];
    float dt = (raw > 20.f) ? raw : log1pf(expf(raw));
    int row = (b<<12) + l;
    g_dt[r][row] = dt;
    float v = dt;
    #pragma unroll
    for (int off=1; off<32; off<<=1) {
        float n = __shfl_up_sync(0xffffffffu, v, off);
        if ((t&31) >= off) v += n;
    }
    if ((t&31)==31) wsum[t>>5] = v;
    __syncthreads();
    float pre = 0.f;
    for (int w=0; w < (t>>5); w++) pre += wsum[w];
    g_cd[r][row] = v + pre;
}

// ---------------- 7) per-chunk state contribution ----------------
__global__ void k_chunkstate(const float* __restrict__ A_log) {
    extern __shared__ float sm[];
    float* xw  = sm;                // 128x65
    float* Bs  = sm + 128*65;       // 128x65
    float* wsm = sm + 2*128*65;     // 128
    int r = blockIdx.z, b = blockIdx.y, ch = blockIdx.x;
    float A = __expf(A_log[r]);
    int rowb = (b<<12) + ch*128;
    if (threadIdx.x < 128) {
        int s = threadIdx.x;
        float cdl = g_cd[r][rowb+127];
        wsm[s] = __expf(-A*(cdl - g_cd[r][rowb+s])) * g_dt[r][rowb+s];
    }
    __syncthreads();
    for (int i = threadIdx.x; i < 8192; i += 256) {
        int p = i >> 7, s = i & 127;
        xw[s*65+p] = g_xbcT[r][(size_t)p*BL + rowb + s] * wsm[s];
        Bs[s*65+p] = g_xbcT[r][(size_t)(64+p)*BL + rowb + s];
    }
    __syncthreads();
    int tp = (threadIdx.x >> 4) << 2;
    int tn = (threadIdx.x & 15) << 2;
    float acc[4][4];
    #pragma unroll
    for (int i=0;i<4;i++)
        #pragma unroll
        for (int j=0;j<4;j++) acc[i][j]=0.f;
    for (int s=0;s<128;s++){
        float xv[4], bv[4];
        #pragma unroll
        for (int i=0;i<4;i++){ xv[i]=xw[s*65+tp+i]; bv[i]=Bs[s*65+tn+i]; }
        #pragma unroll
        for (int i=0;i<4;i++)
            #pragma unroll
            for (int j=0;j<4;j++) acc[i][j] += xv[i]*bv[j];
    }
    size_t Sb = (size_t)(b*NCHK+ch)*4096;
    #pragma unroll
    for (int i=0;i<4;i++)
        #pragma unroll
        for (int j=0;j<4;j++)
            g_S[r][Sb + (tp+i)*64 + tn + j] = acc[i][j];
}

// ---------------- 8) tiny sequential scan over 32 chunks ----------------
__global__ void k_chunkscan(const float* __restrict__ A_log) {
    int b = blockIdx.x, r = blockIdx.y;
    float A = __expf(A_log[r]);
    float h[16];
    #pragma unroll
    for (int i=0;i<16;i++) h[i]=0.f;
    for (int ch=0; ch<NCHK; ch++){
        float cdl = g_cd[r][(b<<12)+ch*128+127];
        float pl = __expf(-A*cdl);
        size_t base = (size_t)(b*NCHK+ch)*4096;
        #pragma unroll
        for (int i=0;i<16;i++){
            int e = i*256 + threadIdx.x;
            g_Hin[r][base+e] = h[i];
            h[i] = pl*h[i] + g_S[r][base+e];
        }
    }
}

// ---------------- 9) per-chunk output (512 threads) ----------------
__global__ void __launch_bounds__(512) k_output(const float* __restrict__ A_log,
                         const float* __restrict__ Dp, const float* __restrict__ normw) {
    extern __shared__ float sm[];
    float* Cst = sm;                   // [64][136]
    float* Bst = Cst + 64*136;         // [64][136]  (later xs[128][68])
    float* Msm = Bst + 64*136;         // [128][132]
    float* Hst = Msm + 128*132;        // [64][72]
    float* cds = Hst + 64*72;          // 128
    float* dts = cds + 128;            // 128
    int r = blockIdx.z, b = blockIdx.y, chl = blockIdx.x;
    float A = __expf(A_log[r]);
    float Dv = Dp[r];
    int rowb = (b<<12) + chl*128;
    int tid = threadIdx.x;
    for (int i = tid; i < 8192; i += 512) {
        int n = i >> 7, s = i & 127;
        Cst[n*136+s] = g_xbcT[r][(size_t)(128+n)*BL + rowb + s];
        Bst[n*136+s] = g_xbcT[r][(size_t)(64+n)*BL + rowb + s];
    }
    for (int i = tid; i < 4096; i += 512) {
        int p = i >> 6, n = i & 63;
        Hst[n*72+p] = g_Hin[r][(size_t)(b*NCHK+chl)*4096 + p*64 + n];
    }
    if (tid < 128) {
        cds[tid] = g_cd[r][rowb+tid];
        dts[tid] = g_dt[r][rowb+tid];
    }
    __syncthreads();

    // --- M build: 8x4 register tiles over 512 threads, causal skip ---
    {
        int rg = tid >> 5;   // 0..15 -> rows rg*8..+7
        int cg = tid & 31;   // 0..31 -> cols cg*4..+3
        float m[8][4];
        #pragma unroll
        for (int i=0;i<8;i++)
            #pragma unroll
            for (int j=0;j<4;j++) m[i][j]=0.f;
        if (cg*4 <= rg*8+7) {
            for (int n=0;n<64;n++){
                float4 c0 = *(const float4*)&Cst[n*136 + rg*8];
                float4 c1 = *(const float4*)&Cst[n*136 + rg*8 + 4];
                float4 b0 = *(const float4*)&Bst[n*136 + cg*4];
                float cv[8] = {c0.x,c0.y,c0.z,c0.w,c1.x,c1.y,c1.z,c1.w};
                float bv[4] = {b0.x,b0.y,b0.z,b0.w};
                #pragma unroll
                for (int i=0;i<8;i++)
                    #pragma unroll
                    for (int j=0;j<4;j++) m[i][j] += cv[i]*bv[j];
            }
            float cdR = cds[rg*8];
            float er[8], ec[4];
            #pragma unroll
            for (int i=0;i<8;i++) er[i] = __expf(-A*(cds[rg*8+i]-cdR));
            #pragma unroll
            for (int j=0;j<4;j++){ int s=cg*4+j; ec[j] = __expf(-A*(cdR - cds[s])) * dts[s]; }
            #pragma unroll
            for (int i=0;i<8;i++)
                #pragma unroll
                for (int j=0;j<4;j++){
                    if (cg*4+j > rg*8+i) m[i][j] = 0.f;
                    else m[i][j] *= er[i]*ec[j];
                }
        }
        #pragma unroll
        for (int i=0;i<8;i++)
            *(float4*)&Msm[(rg*8+i)*132 + cg*4] = make_float4(m[i][0],m[i][1],m[i][2],m[i][3]);
    }

    // --- Y_inter: acc[2][8] over (t,p) ---
    int tg = tid >> 3;   // 0..63 -> 2 t each
    int tq = tid & 7;    // 0..7  -> 8 p each
    float acc[2][8];
    #pragma unroll
    for (int i=0;i<2;i++)
        #pragma unroll
        for (int j=0;j<8;j++) acc[i][j]=0.f;
    for (int n=0;n<64;n++){
        float cv[2];
        cv[0] = Cst[n*136 + tg*2];
        cv[1] = Cst[n*136 + tg*2 + 1];
        float4 h0 = *(const float4*)&Hst[n*72 + tq*8];
        float4 h1 = *(const float4*)&Hst[n*72 + tq*8 + 4];
        float hv[8] = {h0.x,h0.y,h0.z,h0.w,h1.x,h1.y,h1.z,h1.w};
        #pragma unroll
        for (int i=0;i<2;i++)
            #pragma unroll
            for (int j=0;j<8;j++) acc[i][j] += cv[i]*hv[j];
    }
    #pragma unroll
    for (int i=0;i<2;i++){
        float f = __expf(-A*cds[tg*2+i]);
        #pragma unroll
        for (int j=0;j<8;j++) acc[i][j] *= f;
    }
    __syncthreads();
    // reload xs over Bst: xs[s][p] stride 68 (float4-aligned)
    float* xs = Bst;
    for (int i = tid; i < 8192; i += 512) {
        int p = i >> 7, s = i & 127;
        xs[s*68+p] = g_xbcT[r][(size_t)p*BL + rowb + s];
    }
    __syncthreads();
    // --- Y_intra: M @ xs ---
    for (int s2=0;s2<128;s2++){
        float mv[2];
        mv[0] = Msm[(tg*2)*132 + s2];
        mv[1] = Msm[(tg*2+1)*132 + s2];
        float4 x0 = *(const float4*)&xs[s2*68 + tq*8];
        float4 x1 = *(const float4*)&xs[s2*68 + tq*8 + 4];
        float xv[8] = {x0.x,x0.y,x0.z,x0.w,x1.x,x1.y,x1.z,x1.w};
        #pragma unroll
        for (int i=0;i<2;i++)
            #pragma unroll
            for (int j=0;j<8;j++) acc[i][j] += mv[i]*xv[j];
    }
    // epilogue: + D*xs, gate silu(z), RMSnorm, store
    #pragma unroll
    for (int i=0;i<2;i++){
        int t = tg*2+i;
        size_t zb = (size_t)(rowb+t)*64 + tq*8;
        float y[8]; float ss = 0.f;
        #pragma unroll
        for (int j=0;j<8;j++){
            float yv = acc[i][j] + Dv * xs[t*68 + tq*8 + j];
            float zv = g_z[r][zb + j];
            yv *= zv * sigf(zv);
            y[j] = yv; ss += yv*yv;
        }
        ss += __shfl_xor_sync(0xffffffffu, ss, 1);
        ss += __shfl_xor_sync(0xffffffffu, ss, 2);
        ss += __shfl_xor_sync(0xffffffffu, ss, 4);
        float sc = rsqrtf(ss*(1.f/64.f) + 1e-5f);
        #pragma unroll
        for (int j=0;j<8;j++)
            g_yg[r][zb + j] = y[j] * sc * normw[r*64 + tq*8 + j];
    }
}

// ---------------- 10) combined out-weights ----------------
__global__ void k_prepW(const float* __restrict__ Wout, const float* __restrict__ Wfo) {
    __shared__ float v[32];
    int kk = blockIdx.x; int rr = kk >> 6; int p = kk & 63;
    if (threadIdx.x < 32) v[threadIdx.x] = Wout[rr*2048 + p*32 + threadIdx.x];
    __syncthreads();
    int c = threadIdx.x;
    float acc = 0.f;
    #pragma unroll
    for (int d=0;d<32;d++) acc += v[d]*Wfo[d*128 + c];
    g_Wcomb[kk*128 + c] = acc;
}

// ---------------- 11) fused out-proj + fc_out (64-out x 128-l tiles) ----------------
__global__ void __launch_bounds__(256) k_outfuse() {
    extern __shared__ float sm[];
    float* Wsm = sm;            // [128 k][64 o]
    float* ysm = sm + 8192;     // [128 k][132 l]
    int row0 = blockIdx.x << 7;
    int o0 = blockIdx.y << 6;
    int b = row0 >> 12; int l0 = row0 & 4095;
    for (int i = threadIdx.x; i < 8192; i += 256) {
        int k = i >> 6, oo = i & 63;
        Wsm[i] = g_Wcomb[k*128 + o0 + oo];
    }
    for (int i = threadIdx.x; i < 8192; i += 256) {
        int row = i >> 6, k = i & 63;
        ysm[k*132 + row] = g_yg[0][(size_t)(row0+row)*64 + k];
    }
    for (int i = threadIdx.x; i < 8192; i += 256) {
        int row = i >> 6, k = i & 63;
        int l = (row0+row) & 4095;
        ysm[(64+k)*132 + row] = g_yg[1][(size_t)((b<<12) + (4095-l))*64 + k];
    }
    __syncthreads();
    int og = threadIdx.x & 15;   // 4 outs each
    int lg = threadIdx.x >> 4;   // 8 ls each
    float acc[4][8];
    #pragma unroll
    for (int a=0;a<4;a++)
        #pragma unroll
        for (int c2=0;c2<8;c2++) acc[a][c2]=0.f;
    for (int k=0;k<128;k++){
        float4 w0 = *(const float4*)&Wsm[k*64 + og*4];
        float4 y0 = *(const float4*)&ysm[k*132 + lg*8];
        float4 y1 = *(const float4*)&ysm[k*132 + lg*8 + 4];
        float wv[4] = {w0.x,w0.y,w0.z,w0.w};
        float yv[8] = {y0.x,y0.y,y0.z,y0.w,y1.x,y1.y,y1.z,y1.w};
        #pragma unroll
        for (int a=0;a<4;a++)
            #pragma unroll
            for (int c2=0;c2<8;c2++) acc[a][c2] += wv[a]*yv[c2];
    }
    #pragma unroll
    for (int a=0;a<4;a++){
        int c = o0 + og*4 + a;
        float* dp = &g_o2[((size_t)b*CC + c)*HWD + l0 + lg*8];
        #pragma unroll
        for (int c2=0;c2<8;c2++) dp[c2] = acc[a][c2];
    }
}

// ---------------- 12) batchnorm stats ----------------
__global__ void k_bnstats(const float* __restrict__ bn_g, const float* __restrict__ bn_b) {
    __shared__ float rs[256], rq[256];
    int c2 = blockIdx.x;
    float s1=0.f, s2=0.f;
    for (int b=0;b<BB;b++){
        const float* p = g_o2 + ((size_t)b*CC + c2)*HWD;
        for (int l=threadIdx.x; l<HWD; l+=256){ float v=p[l]; s1+=v; s2+=v*v; }
    }
    rs[threadIdx.x]=s1; rq[threadIdx.x]=s2;
    __syncthreads();
    for (int off=128; off>0; off>>=1){
        if ((int)threadIdx.x < off){ rs[threadIdx.x]+=rs[threadIdx.x+off]; rq[threadIdx.x]+=rq[threadIdx.x+off]; }
        __syncthreads();
    }
    if (threadIdx.x==0){
        float mu  = rs[0]*(1.f/32768.f);
        float var = rq[0]*(1.f/32768.f) - mu*mu;
        float a = rsqrtf(var + 1e-5f) * bn_g[c2];
        g_bnA[c2] = a;
        g_bnT[c2] = bn_b[c2] - mu*a;
    }
}

// ---------------- 13) fold BN into conv4 ----------------
__global__ void k_prep4(const float* __restrict__ cw, const float* __restrict__ cb) {
    int o = threadIdx.x;  // 128
    float bacc = cb[o];
    for (int i=0;i<128;i++){
        float w = cw[i*128+o];
        g_W4[i*128+o] = g_bnA[i]*w;
        bacc += g_bnT[i]*w;
    }
    g_b4[o] = bacc;
}

// ---------------- 14) conv4 + sigmoid gate + residual (64-out x 128-l tiles) ----------------
__global__ void __launch_bounds__(256) k_conv4(const float* __restrict__ x, float* __restrict__ out) {
    extern __shared__ float sm[];
    float* Wsm = sm;            // [128 i][64 o]
    float* xsm = sm + 8192;     // [128 ch][128 l]
    int lt = blockIdx.x, ot = blockIdx.y, b = blockIdx.z;
    int l0 = lt << 7; int o0 = ot << 6;
    const float* sb = g_o2 + (size_t)b*CC*HWD;
    for (int i = threadIdx.x; i < 8192; i += 256) {
        int ii = i >> 6, oo = i & 63;
        Wsm[i] = g_W4[ii*128 + o0 + oo];
    }
    for (int i = threadIdx.x; i < 16384; i += 256) {
        int ch = i >> 7, l = i & 127;
        xsm[i] = sb[ch*HWD + l0 + l];
    }
    __syncthreads();
    int og = threadIdx.x & 15;
    int lg = threadIdx.x >> 4;
    float acc[4][8];
    #pragma unroll
    for (int a=0;a<4;a++)
        #pragma unroll
        for (int c2=0;c2<8;c2++) acc[a][c2]=0.f;
    for (int i=0;i<128;i++){
        float4 w0 = *(const float4*)&Wsm[i*64 + og*4];
        float4 x0 = *(const float4*)&xsm[i*128 + lg*8];
        float4 x1 = *(const float4*)&xsm[i*128 + lg*8 + 4];
        float wv[4] = {w0.x,w0.y,w0.z,w0.w};
        float xv[8] = {x0.x,x0.y,x0.z,x0.w,x1.x,x1.y,x1.z,x1.w};
        #pragma unroll
        for (int a=0;a<4;a++)
            #pragma unroll
            for (int c2=0;c2<8;c2++) acc[a][c2] += wv[a]*xv[c2];
    }
    #pragma unroll
    for (int a=0;a<4;a++){
        int o = o0 + og*4 + a; float bv = g_b4[o];
        size_t base = ((size_t)b*CC + o)*HWD + l0 + lg*8;
        #pragma unroll
        for (int c2=0;c2<8;c2++){
            float v = acc[a][c2] + bv;
            float g = sigf(v);
            float xr = x[base+c2];
            out[base+c2] = g*xr + xr;
        }
    }
}

// ---------------- launch ----------------
extern "C" void kernel_launch(void* const* d_in, const int* in_sizes, int n_in,
                              void* d_out, int out_size) {
    const float* x        = (const float*)d_in[0];
    const float* lin1_w   = (const float*)d_in[1];
    const float* lin1_b   = (const float*)d_in[2];
    const float* dw_w     = (const float*)d_in[3];
    const float* dw_b     = (const float*)d_in[4];
    const float* fc_in_w  = (const float*)d_in[5];
    const float* mam_in_w = (const float*)d_in[6];
    const float* mam_cw   = (const float*)d_in[7];
    const float* mam_cb   = (const float*)d_in[8];
    const float* mam_dtb  = (const float*)d_in[9];
    const float* mam_Alog = (const float*)d_in[10];
    const float* mam_D    = (const float*)d_in[11];
    const float* mam_nw   = (const float*)d_in[12];
    const float* mam_ow   = (const float*)d_in[13];
    const float* fc_out_w = (const float*)d_in[14];
    const float* bn_g     = (const float*)d_in[15];
    const float* bn_b     = (const float*)d_in[16];
    const float* conv4_w  = (const float*)d_in[17];
    const float* conv4_b  = (const float*)d_in[18];
    float* out = (float*)d_out;

    cudaFuncSetAttribute(k_lin1,       cudaFuncAttributeMaxDynamicSharedMemorySize, 98304);
    cudaFuncSetAttribute(k_conv4,      cudaFuncAttributeMaxDynamicSharedMemorySize, 98304);
    cudaFuncSetAttribute(k_fcin,       cudaFuncAttributeMaxDynamicSharedMemorySize, 81920);
    cudaFuncSetAttribute(k_inproj,     cudaFuncAttributeMaxDynamicSharedMemorySize, SI_TOT*4);
    cudaFuncSetAttribute(k_chunkstate, cudaFuncAttributeMaxDynamicSharedMemorySize, 67072);
    cudaFuncSetAttribute(k_output,     cudaFuncAttributeMaxDynamicSharedMemorySize, 156672);
    cudaFuncSetAttribute(k_outfuse,    cudaFuncAttributeMaxDynamicSharedMemorySize, 100352);

    k_lin1<<<dim3(32,2,BB), 256, 98304>>>(x, lin1_w, lin1_b);
    k_dw<<<BB*CC*HWD/256, 256>>>(dw_w, dw_b);
    k_fcin<<<dim3(32,BB), 256, 81920>>>(fc_in_w);
    k_inproj<<<dim3(BL/64, 2), 256, SI_TOT*4>>>(mam_in_w, mam_cw, mam_cb);
    k_dtscan<<<dim3(NCHK, BB, 2), 128>>>(mam_dtb, mam_in_w);
    k_chunkstate<<<dim3(NCHK, BB, 2), 256, 67072>>>(mam_Alog);
    k_chunkscan<<<dim3(BB, 2), 256>>>(mam_Alog);
    k_output<<<dim3(NCHK, BB, 2), 512, 156672>>>(mam_Alog, mam_D, mam_nw);
    k_prepW<<<128, 128>>>(mam_ow, fc_out_w);
    k_outfuse<<<dim3(BL/128, 2), 256, 100352>>>();
    k_bnstats<<<CC, 256>>>(bn_g, bn_b);
    k_prep4<<<1, CC>>>(conv4_w, conv4_b);
    k_conv4<<<dim3(32,2,BB), 256, 98304>>>(x, out);
}

// round 16
// speedup vs baseline: 1.1935x; 1.1935x over previous
#include <cuda_runtime.h>
#include <cstdint>

#define BB   8
#define CC   128
#define HWD  4096
#define LL   4096
#define DMI  32
#define DII  64
#define DSS  64
#define NCHK 32
#define BL   (BB*LL)   // 32768

// ---------------- scratch (device globals) ----------------
__device__ float g_t1[BB*CC*HWD];
__device__ float g_o1[BB*CC*HWD];
__device__ float g_s[BL*DMI];
__device__ float g_z[2][BL*DII];
__device__ float g_xbcT[2][192*BL];     // post conv+silu, [ch][row]; ch: 0..63 xs, 64..127 B, 128..191 C
__device__ float g_dt[2][BL];
__device__ float g_cd[2][BL];
__device__ float g_S[2][BB*NCHK*DII*DSS];
__device__ float g_Hin[2][BB*NCHK*DII*DSS];
__device__ float g_yg[2][BL*DII];
__device__ float g_o2[BB*CC*HWD];
__device__ float g_bnA[CC], g_bnT[CC];
__device__ float g_W4[CC*CC], g_b4[CC];
__device__ float g_Wcomb[CC*CC];

__device__ __forceinline__ float sigf(float v){ return 1.f/(1.f+__expf(-v)); }

// ---------------- 1) lin1: per-pixel 128->128 GEMM + bias (64-out x 128-l tiles) ----------------
__global__ void __launch_bounds__(256) k_lin1(const float* __restrict__ x,
                       const float* __restrict__ W, const float* __restrict__ bias) {
    extern __shared__ float sm[];
    float* Wsm = sm;            // [128 i][64 o]
    float* xsm = sm + 8192;     // [128 ch][128 l]
    int lt = blockIdx.x, ot = blockIdx.y, b = blockIdx.z;
    int l0 = lt << 7; int o0 = ot << 6;
    const float* sb = x + (size_t)b*CC*HWD;
    for (int i = threadIdx.x; i < 8192; i += 256) {
        int ii = i >> 6, oo = i & 63;
        Wsm[i] = W[ii*128 + o0 + oo];
    }
    for (int i = threadIdx.x; i < 16384; i += 256) {
        int ch = i >> 7, l = i & 127;
        xsm[i] = sb[ch*HWD + l0 + l];
    }
    __syncthreads();
    int og = threadIdx.x & 15;    // 4 outs each
    int lg = threadIdx.x >> 4;    // 8 ls each
    float acc[4][8];
    #pragma unroll
    for (int a=0;a<4;a++)
        #pragma unroll
        for (int c2=0;c2<8;c2++) acc[a][c2]=0.f;
    for (int i=0;i<128;i++){
        float4 w0 = *(const float4*)&Wsm[i*64 + og*4];
        float4 x0 = *(const float4*)&xsm[i*128 + lg*8];
        float4 x1 = *(const float4*)&xsm[i*128 + lg*8 + 4];
        float wv[4] = {w0.x,w0.y,w0.z,w0.w};
        float xv[8] = {x0.x,x0.y,x0.z,x0.w,x1.x,x1.y,x1.z,x1.w};
        #pragma unroll
        for (int a=0;a<4;a++)
            #pragma unroll
            for (int c2=0;c2<8;c2++) acc[a][c2] += wv[a]*xv[c2];
    }
    #pragma unroll
    for (int a=0;a<4;a++){
        int o = o0 + og*4 + a; float bv = bias[o];
        float* dp = &g_t1[((size_t)b*CC + o)*HWD + l0 + lg*8];
        #pragma unroll
        for (int c2=0;c2<8;c2++) dp[c2] = acc[a][c2] + bv;
    }
}

// ---------------- 2) 3x3 depthwise conv + bias + silu ----------------
__global__ void k_dw(const float* __restrict__ wdw, const float* __restrict__ bdw) {
    int idx = blockIdx.x*256 + threadIdx.x;
    int l = idx & 4095; int bc = idx >> 12; int c = bc & 127;
    int hh = l >> 6; int ww = l & 63;
    const float* src = g_t1 + (size_t)bc*HWD;
    const float* wp = wdw + c*9;
    float acc = bdw[c];
    #pragma unroll
    for (int dy=-1; dy<=1; dy++){
        int y = hh+dy;
        if ((unsigned)y < 64u) {
            #pragma unroll
            for (int dx=-1; dx<=1; dx++){
                int x2 = ww+dx;
                if ((unsigned)x2 < 64u)
                    acc += src[y*64+x2] * wp[(dy+1)*3 + (dx+1)];
            }
        }
    }
    g_o1[idx] = acc * sigf(acc);
}

// ---------------- 3) fc_in: (b,l) 128->32 ----------------
__global__ void k_fcin(const float* __restrict__ Wfc) {
    extern __shared__ float sm[];
    float* xsm = sm;          // 128ch x 128l
    float* Wsm = sm + 16384;  // 128x32
    int b = blockIdx.y; int l0 = blockIdx.x << 7;
    for (int i = threadIdx.x; i < 16384; i += 256){
        int ch = i>>7, l = i&127;
        xsm[i] = g_o1[((size_t)b*CC+ch)*HWD + l0 + l];
    }
    for (int i = threadIdx.x; i < 4096; i += 256) Wsm[i] = Wfc[i];
    __syncthreads();
    int tl = (threadIdx.x & 31)*4;
    int td = (threadIdx.x >> 5)*4;
    float acc[4][4];
    #pragma unroll
    for (int i=0;i<4;i++)
        #pragma unroll
        for (int j=0;j<4;j++) acc[i][j]=0.f;
    for (int c2=0;c2<128;c2++){
        float4 xv = *(const float4*)&xsm[c2*128 + tl];
        float4 wv = *(const float4*)&Wsm[c2*32 + td];
        float xa[4] = {xv.x,xv.y,xv.z,xv.w};
        float wa[4] = {wv.x,wv.y,wv.z,wv.w};
        #pragma unroll
        for (int i=0;i<4;i++)
            #pragma unroll
            for (int j=0;j<4;j++) acc[i][j] += xa[i]*wa[j];
    }
    #pragma unroll
    for (int i=0;i<4;i++){
        float4 o4 = make_float4(acc[i][0],acc[i][1],acc[i][2],acc[i][3]);
        *(float4*)&g_s[(size_t)((b<<12) + l0 + tl + i)*32 + td] = o4;
    }
}

// ---------------- 4) FUSED in-projection GEMM + causal conv1d + silu + dt/cumsum ----------------
// smem float offsets:
//  Wsm    0      [32][256]
//  sT     8192   [32][136]
//  wdt    12544  [32]
//  wsum   12576  [4]
//  cwsm   12592  [768]
//  cbsm   13360  [192]
//  xbcr   13552  [192][133]  (idx = ch*133 + 4 + (l-l0); halo l0-3..l0-1 at +1..+3)
#define SM_ST   8192
#define SM_WDT  12544
#define SM_WSUM 12576
#define SM_CW   12592
#define SM_CB   13360
#define SM_XB   13552
__global__ void __launch_bounds__(512) k_inproj(const float* __restrict__ Win,
        const float* __restrict__ cw, const float* __restrict__ cb,
        const float* __restrict__ dtb) {
    extern __shared__ float sm[];
    int r = blockIdx.y; int row0 = blockIdx.x << 7;
    int b = row0 >> 12; int l0 = row0 & 4095;
    int tid = threadIdx.x;
    const float* Wr = Win + r*8224;
    for (int i = tid; i < 8192; i += 512) {
        int k = i >> 8, o = i & 255;
        sm[i] = Wr[k*257 + o];
    }
    for (int i = tid; i < 4096; i += 512) {
        int row = i >> 5, k = i & 31;
        int l = l0 + row;
        int lsel = r ? (4095 - l) : l;
        sm[SM_ST + k*136 + row] = g_s[(size_t)((b<<12)+lsel)*32 + k];
    }
    if (tid < 32)  sm[SM_WDT + tid] = Wr[tid*257 + 256];
    for (int i = tid; i < 768; i += 512) sm[SM_CW + i] = cw[r*768 + i];
    if (tid < 192) sm[SM_CB + tid] = cb[r*192 + tid];
    __syncthreads();

    int tr = tid >> 5;   // 0..15 -> rows tr*8..+7
    int tc = tid & 31;   // cols: tc + 32*j, j=0..7
    float acc[8][8];
    #pragma unroll
    for (int i=0;i<8;i++)
        #pragma unroll
        for (int j=0;j<8;j++) acc[i][j]=0.f;
    for (int k=0;k<32;k++){
        float4 a0 = *(const float4*)&sm[SM_ST + k*136 + tr*8];
        float4 a1 = *(const float4*)&sm[SM_ST + k*136 + tr*8 + 4];
        float av[8] = {a0.x,a0.y,a0.z,a0.w,a1.x,a1.y,a1.z,a1.w};
        float bv[8];
        #pragma unroll
        for (int j=0;j<8;j++) bv[j] = sm[k*256 + tc + 32*j];
        #pragma unroll
        for (int i=0;i<8;i++)
            #pragma unroll
            for (int j=0;j<8;j++) acc[i][j] += av[i]*bv[j];
    }
    // z (cols tc and tc+32, i.e. j=0,1) -> global; xbc (j>=2) -> smem
    #pragma unroll
    for (int i=0;i<8;i++){
        int grow = row0 + tr*8 + i;
        g_z[r][(size_t)grow*64 + tc]      = acc[i][0];
        g_z[r][(size_t)grow*64 + tc + 32] = acc[i][1];
    }
    #pragma unroll
    for (int j=2;j<8;j++){
        int ch = (j-2)*32 + tc;
        #pragma unroll
        for (int i=0;i<8;i++)
            sm[SM_XB + ch*133 + 4 + tr*8 + i] = acc[i][j];
    }
    // halo rows l0-3..l0-1 (recompute or zero at sequence start)
    for (int i = tid; i < 576; i += 512) {
        int h = i / 192; int ch = i - h*192;
        int l = l0 - 3 + h;
        float v = 0.f;
        if (l >= 0) {
            int lsel = r ? (4095 - l) : l;
            const float* srow = &g_s[(size_t)((b<<12)+lsel)*32];
            #pragma unroll
            for (int k=0;k<32;k++) v += srow[k]*sm[k*256 + 64 + ch];
        }
        sm[SM_XB + ch*133 + 1 + h] = v;
    }
    __syncthreads();

    // dt + softplus + in-chunk cumsum (block == one chunk)
    float vscan = 0.f;
    if (tid < 128) {
        float raw = dtb[r];
        #pragma unroll
        for (int k=0;k<32;k++) raw += sm[SM_ST + k*136 + tid]*sm[SM_WDT + k];
        float dt = (raw > 20.f) ? raw : log1pf(expf(raw));
        g_dt[r][row0 + tid] = dt;
        vscan = dt;
        #pragma unroll
        for (int off=1; off<32; off<<=1) {
            float n = __shfl_up_sync(0xffffffffu, vscan, off);
            if ((tid&31) >= off) vscan += n;
        }
        if ((tid&31)==31) sm[SM_WSUM + (tid>>5)] = vscan;
    }
    __syncthreads();
    if (tid < 128) {
        float pre = 0.f;
        for (int w=0; w < (tid>>5); w++) pre += sm[SM_WSUM + w];
        g_cd[r][row0 + tid] = vscan + pre;
    }

    // causal conv (4 taps) + silu -> g_xbcT
    for (int i = tid; i < 24576; i += 512) {
        int ch = i >> 7; int rowi = i & 127;
        const float* xp = &sm[SM_XB + ch*133 + 4 + rowi];
        const float* w  = &sm[SM_CW + ch*4];
        float a = sm[SM_CB + ch] + xp[-3]*w[0] + xp[-2]*w[1] + xp[-1]*w[2] + xp[0]*w[3];
        g_xbcT[r][(size_t)ch*BL + row0 + rowi] = a * sigf(a);
    }
}

// ---------------- 7) per-chunk state contribution ----------------
__global__ void k_chunkstate(const float* __restrict__ A_log) {
    extern __shared__ float sm[];
    float* xw  = sm;                // 128x65
    float* Bs  = sm + 128*65;       // 128x65
    float* wsm = sm + 2*128*65;     // 128
    int r = blockIdx.z, b = blockIdx.y, ch = blockIdx.x;
    float A = __expf(A_log[r]);
    int rowb = (b<<12) + ch*128;
    if (threadIdx.x < 128) {
        int s = threadIdx.x;
        float cdl = g_cd[r][rowb+127];
        wsm[s] = __expf(-A*(cdl - g_cd[r][rowb+s])) * g_dt[r][rowb+s];
    }
    __syncthreads();
    for (int i = threadIdx.x; i < 8192; i += 256) {
        int p = i >> 7, s = i & 127;
        xw[s*65+p] = g_xbcT[r][(size_t)p*BL + rowb + s] * wsm[s];
        Bs[s*65+p] = g_xbcT[r][(size_t)(64+p)*BL + rowb + s];
    }
    __syncthreads();
    int tp = (threadIdx.x >> 4) << 2;
    int tn = (threadIdx.x & 15) << 2;
    float acc[4][4];
    #pragma unroll
    for (int i=0;i<4;i++)
        #pragma unroll
        for (int j=0;j<4;j++) acc[i][j]=0.f;
    for (int s=0;s<128;s++){
        float xv[4], bv[4];
        #pragma unroll
        for (int i=0;i<4;i++){ xv[i]=xw[s*65+tp+i]; bv[i]=Bs[s*65+tn+i]; }
        #pragma unroll
        for (int i=0;i<4;i++)
            #pragma unroll
            for (int j=0;j<4;j++) acc[i][j] += xv[i]*bv[j];
    }
    size_t Sb = (size_t)(b*NCHK+ch)*4096;
    #pragma unroll
    for (int i=0;i<4;i++)
        #pragma unroll
        for (int j=0;j<4;j++)
            g_S[r][Sb + (tp+i)*64 + tn + j] = acc[i][j];
}

// ---------------- 8) chunk scan, parallel over state elements (16 segs x 256 thr) ----------------
__global__ void k_chunkscan(const float* __restrict__ A_log) {
    int b = blockIdx.x, r = blockIdx.y, seg = blockIdx.z;
    float A = __expf(A_log[r]);
    int e = seg*256 + threadIdx.x;   // 0..4095
    float h = 0.f;
    #pragma unroll 4
    for (int ch=0; ch<NCHK; ch++){
        float cdl = g_cd[r][(b<<12)+ch*128+127];
        float pl = __expf(-A*cdl);
        size_t base = (size_t)(b*NCHK+ch)*4096 + e;
        g_Hin[r][base] = h;
        h = pl*h + g_S[r][base];
    }
}

// ---------------- 9) per-chunk output ----------------
__global__ void __launch_bounds__(256) k_output(const float* __restrict__ A_log,
                         const float* __restrict__ Dp, const float* __restrict__ normw) {
    extern __shared__ float sm[];
    float* Cst = sm;                   // [64][136]
    float* Bst = Cst + 64*136;         // [64][136]  (later xs[128][68])
    float* Msm = Bst + 64*136;         // [128][132]
    float* Hst = Msm + 128*132;        // [64][72]
    float* cds = Hst + 64*72;          // 128
    float* dts = cds + 128;            // 128
    int r = blockIdx.z, b = blockIdx.y, chl = blockIdx.x;
    float A = __expf(A_log[r]);
    float Dv = Dp[r];
    int rowb = (b<<12) + chl*128;
    int tid = threadIdx.x;
    for (int i = tid; i < 8192; i += 256) {
        int n = i >> 7, s = i & 127;
        Cst[n*136+s] = g_xbcT[r][(size_t)(128+n)*BL + rowb + s];
        Bst[n*136+s] = g_xbcT[r][(size_t)(64+n)*BL + rowb + s];
    }
    for (int i = tid; i < 4096; i += 256) {
        int p = i >> 6, n = i & 63;
        Hst[n*72+p] = g_Hin[r][(size_t)(b*NCHK+chl)*4096 + p*64 + n];
    }
    if (tid < 128) {
        cds[tid] = g_cd[r][rowb+tid];
        dts[tid] = g_dt[r][rowb+tid];
    }
    __syncthreads();

    // --- M build: 8x8 register tiles, causal skip ---
    {
        int rg = tid >> 4, cg = tid & 15;
        float m[8][8];
        #pragma unroll
        for (int i=0;i<8;i++)
            #pragma unroll
            for (int j=0;j<8;j++) m[i][j]=0.f;
        if (cg <= rg) {
            for (int n=0;n<64;n++){
                float4 c0 = *(const float4*)&Cst[n*136 + rg*8];
                float4 c1 = *(const float4*)&Cst[n*136 + rg*8 + 4];
                float4 b0 = *(const float4*)&Bst[n*136 + cg*8];
                float4 b1 = *(const float4*)&Bst[n*136 + cg*8 + 4];
                float cv[8] = {c0.x,c0.y,c0.z,c0.w,c1.x,c1.y,c1.z,c1.w};
                float bv[8] = {b0.x,b0.y,b0.z,b0.w,b1.x,b1.y,b1.z,b1.w};
                #pragma unroll
                for (int i=0;i<8;i++)
                    #pragma unroll
                    for (int j=0;j<8;j++) m[i][j] += cv[i]*bv[j];
            }
            float cdR = cds[rg*8];
            float er[8], ec[8];
            #pragma unroll
            for (int i=0;i<8;i++) er[i] = __expf(-A*(cds[rg*8+i]-cdR));
            #pragma unroll
            for (int j=0;j<8;j++){ int s=cg*8+j; ec[j] = __expf(-A*(cdR - cds[s])) * dts[s]; }
            if (cg == rg) {
                #pragma unroll
                for (int i=0;i<8;i++)
                    #pragma unroll
                    for (int j=0;j<8;j++) if (j > i) m[i][j] = 0.f;
            }
            #pragma unroll
            for (int i=0;i<8;i++)
                #pragma unroll
                for (int j=0;j<8;j++) m[i][j] *= er[i]*ec[j];
        }
        #pragma unroll
        for (int i=0;i<8;i++){
            *(float4*)&Msm[(rg*8+i)*132 + cg*8]     = make_float4(m[i][0],m[i][1],m[i][2],m[i][3]);
            *(float4*)&Msm[(rg*8+i)*132 + cg*8 + 4] = make_float4(m[i][4],m[i][5],m[i][6],m[i][7]);
        }
    }

    // --- Y_inter: acc[4][8] over (t,p) ---
    int tg = tid >> 3;   // 0..31 -> 4 t each
    int tq = tid & 7;    // 0..7  -> 8 p each
    float acc[4][8];
    #pragma unroll
    for (int i=0;i<4;i++)
        #pragma unroll
        for (int j=0;j<8;j++) acc[i][j]=0.f;
    for (int n=0;n<64;n++){
        float4 cv4 = *(const float4*)&Cst[n*136 + tg*4];
        float4 h0 = *(const float4*)&Hst[n*72 + tq*8];
        float4 h1 = *(const float4*)&Hst[n*72 + tq*8 + 4];
        float cv[4] = {cv4.x,cv4.y,cv4.z,cv4.w};
        float hv[8] = {h0.x,h0.y,h0.z,h0.w,h1.x,h1.y,h1.z,h1.w};
        #pragma unroll
        for (int i=0;i<4;i++)
            #pragma unroll
            for (int j=0;j<8;j++) acc[i][j] += cv[i]*hv[j];
    }
    #pragma unroll
    for (int i=0;i<4;i++){
        float f = __expf(-A*cds[tg*4+i]);
        #pragma unroll
        for (int j=0;j<8;j++) acc[i][j] *= f;
    }
    __syncthreads();
    // reload xs over Bst: xs[s][p] with stride 68 (float4-aligned for all s)
    float* xs = Bst;
    for (int i = tid; i < 8192; i += 256) {
        int p = i >> 7, s = i & 127;
        xs[s*68+p] = g_xbcT[r][(size_t)p*BL + rowb + s];
    }
    __syncthreads();
    // --- Y_intra: M @ xs ---
    for (int s2=0;s2<128;s2++){
        float mv[4];
        #pragma unroll
        for (int i=0;i<4;i++) mv[i] = Msm[(tg*4+i)*132 + s2];
        float4 x0 = *(const float4*)&xs[s2*68 + tq*8];
        float4 x1 = *(const float4*)&xs[s2*68 + tq*8 + 4];
        float xv[8] = {x0.x,x0.y,x0.z,x0.w,x1.x,x1.y,x1.z,x1.w};
        #pragma unroll
        for (int i=0;i<4;i++)
            #pragma unroll
            for (int j=0;j<8;j++) acc[i][j] += mv[i]*xv[j];
    }
    // epilogue: + D*xs, gate silu(z), RMSnorm, store
    #pragma unroll
    for (int i=0;i<4;i++){
        int t = tg*4+i;
        size_t zb = (size_t)(rowb+t)*64 + tq*8;
        float y[8]; float ss = 0.f;
        #pragma unroll
        for (int j=0;j<8;j++){
            float yv = acc[i][j] + Dv * xs[t*68 + tq*8 + j];
            float zv = g_z[r][zb + j];
            yv *= zv * sigf(zv);
            y[j] = yv; ss += yv*yv;
        }
        ss += __shfl_xor_sync(0xffffffffu, ss, 1);
        ss += __shfl_xor_sync(0xffffffffu, ss, 2);
        ss += __shfl_xor_sync(0xffffffffu, ss, 4);
        float sc = rsqrtf(ss*(1.f/64.f) + 1e-5f);
        #pragma unroll
        for (int j=0;j<8;j++)
            g_yg[r][zb + j] = y[j] * sc * normw[r*64 + tq*8 + j];
    }
}

// ---------------- 10) combined out-weights: Wcomb[rr*64+p][c] = sum_d Wout[rr][p][d]*Wfo[d][c]
__global__ void k_prepW(const float* __restrict__ Wout, const float* __restrict__ Wfo) {
    __shared__ float v[32];
    int kk = blockIdx.x; int rr = kk >> 6; int p = kk & 63;
    if (threadIdx.x < 32) v[threadIdx.x] = Wout[rr*2048 + p*32 + threadIdx.x];
    __syncthreads();
    int c = threadIdx.x;
    float acc = 0.f;
    #pragma unroll
    for (int d=0;d<32;d++) acc += v[d]*Wfo[d*128 + c];
    g_Wcomb[kk*128 + c] = acc;
}

// ---------------- 11) fused out-proj + fc_out: (y0|y1f) @ Wcomb -> o2(b,c,l) ----------------
__global__ void __launch_bounds__(256) k_outfuse() {
    extern __shared__ float sm[];
    float* Wsm = sm;            // [128][128]
    float* ysm = sm + 16384;    // [128][132]
    int row0 = blockIdx.x << 7;
    int b = row0 >> 12; int l0 = row0 & 4095;
    for (int i = threadIdx.x; i < 16384; i += 256) Wsm[i] = g_Wcomb[i];
    for (int i = threadIdx.x; i < 8192; i += 256) {
        int row = i >> 6, k = i & 63;
        ysm[k*132 + row] = g_yg[0][(size_t)(row0+row)*64 + k];
    }
    for (int i = threadIdx.x; i < 8192; i += 256) {
        int row = i >> 6, k = i & 63;
        int l = (row0+row) & 4095;
        ysm[(64+k)*132 + row] = g_yg[1][(size_t)((b<<12) + (4095-l))*64 + k];
    }
    __syncthreads();
    int to = (threadIdx.x >> 4) << 3;   // out channel group
    int tl = (threadIdx.x & 15) << 3;   // l group
    float acc[8][8];
    #pragma unroll
    for (int a=0;a<8;a++)
        #pragma unroll
        for (int c2=0;c2<8;c2++) acc[a][c2]=0.f;
    for (int k=0;k<128;k++){
        float4 w0 = *(const float4*)&Wsm[k*128+to];
        float4 w1 = *(const float4*)&Wsm[k*128+to+4];
        float4 y0 = *(const float4*)&ysm[k*132+tl];
        float4 y1 = *(const float4*)&ysm[k*132+tl+4];
        float wv[8] = {w0.x,w0.y,w0.z,w0.w,w1.x,w1.y,w1.z,w1.w};
        float yv[8] = {y0.x,y0.y,y0.z,y0.w,y1.x,y1.y,y1.z,y1.w};
        #pragma unroll
        for (int a=0;a<8;a++)
            #pragma unroll
            for (int c2=0;c2<8;c2++) acc[a][c2] += wv[a]*yv[c2];
    }
    #pragma unroll
    for (int a=0;a<8;a++){
        int c = to+a;
        float* dp = &g_o2[((size_t)b*CC + c)*HWD + l0 + tl];
        #pragma unroll
        for (int c2=0;c2<8;c2++) dp[c2] = acc[a][c2];
    }
}

// ---------------- 12) batchnorm stats ----------------
__global__ void k_bnstats(const float* __restrict__ bn_g, const float* __restrict__ bn_b) {
    __shared__ float rs[256], rq[256];
    int c2 = blockIdx.x;
    float s1=0.f, s2=0.f;
    for (int b=0;b<BB;b++){
        const float* p = g_o2 + ((size_t)b*CC + c2)*HWD;
        for (int l=threadIdx.x; l<HWD; l+=256){ float v=p[l]; s1+=v; s2+=v*v; }
    }
    rs[threadIdx.x]=s1; rq[threadIdx.x]=s2;
    __syncthreads();
    for (int off=128; off>0; off>>=1){
        if ((int)threadIdx.x < off){ rs[threadIdx.x]+=rs[threadIdx.x+off]; rq[threadIdx.x]+=rq[threadIdx.x+off]; }
        __syncthreads();
    }
    if (threadIdx.x==0){
        float mu  = rs[0]*(1.f/32768.f);
        float var = rq[0]*(1.f/32768.f) - mu*mu;
        float a = rsqrtf(var + 1e-5f) * bn_g[c2];
        g_bnA[c2] = a;
        g_bnT[c2] = bn_b[c2] - mu*a;
    }
}

// ---------------- 13) fold BN into conv4 ----------------
__global__ void k_prep4(const float* __restrict__ cw, const float* __restrict__ cb) {
    int o = threadIdx.x;  // 128
    float bacc = cb[o];
    for (int i=0;i<128;i++){
        float w = cw[i*128+o];
        g_W4[i*128+o] = g_bnA[i]*w;
        bacc += g_bnT[i]*w;
    }
    g_b4[o] = bacc;
}

// ---------------- 14) conv4 + sigmoid gate + residual (64-out x 128-l tiles) ----------------
__global__ void __launch_bounds__(256) k_conv4(const float* __restrict__ x, float* __restrict__ out) {
    extern __shared__ float sm[];
    float* Wsm = sm;            // [128 i][64 o]
    float* xsm = sm + 8192;     // [128 ch][128 l]
    int lt = blockIdx.x, ot = blockIdx.y, b = blockIdx.z;
    int l0 = lt << 7; int o0 = ot << 6;
    const float* sb = g_o2 + (size_t)b*CC*HWD;
    for (int i = threadIdx.x; i < 8192; i += 256) {
        int ii = i >> 6, oo = i & 63;
        Wsm[i] = g_W4[ii*128 + o0 + oo];
    }
    for (int i = threadIdx.x; i < 16384; i += 256) {
        int ch = i >> 7, l = i & 127;
        xsm[i] = sb[ch*HWD + l0 + l];
    }
    __syncthreads();
    int og = threadIdx.x & 15;
    int lg = threadIdx.x >> 4;
    float acc[4][8];
    #pragma unroll
    for (int a=0;a<4;a++)
        #pragma unroll
        for (int c2=0;c2<8;c2++) acc[a][c2]=0.f;
    for (int i=0;i<128;i++){
        float4 w0 = *(const float4*)&Wsm[i*64 + og*4];
        float4 x0 = *(const float4*)&xsm[i*128 + lg*8];
        float4 x1 = *(const float4*)&xsm[i*128 + lg*8 + 4];
        float wv[4] = {w0.x,w0.y,w0.z,w0.w};
        float xv[8] = {x0.x,x0.y,x0.z,x0.w,x1.x,x1.y,x1.z,x1.w};
        #pragma unroll
        for (int a=0;a<4;a++)
            #pragma unroll
            for (int c2=0;c2<8;c2++) acc[a][c2] += wv[a]*xv[c2];
    }
    #pragma unroll
    for (int a=0;a<4;a++){
        int o = o0 + og*4 + a; float bv = g_b4[o];
        size_t base = ((size_t)b*CC + o)*HWD + l0 + lg*8;
        #pragma unroll
        for (int c2=0;c2<8;c2++){
            float v = acc[a][c2] + bv;
            float g = sigf(v);
            float xr = x[base+c2];
            out[base+c2] = g*xr + xr;
        }
    }
}

// ---------------- launch ----------------
extern "C" void kernel_launch(void* const* d_in, const int* in_sizes, int n_in,
                              void* d_out, int out_size) {
    const float* x        = (const float*)d_in[0];
    const float* lin1_w   = (const float*)d_in[1];
    const float* lin1_b   = (const float*)d_in[2];
    const float* dw_w     = (const float*)d_in[3];
    const float* dw_b     = (const float*)d_in[4];
    const float* fc_in_w  = (const float*)d_in[5];
    const float* mam_in_w = (const float*)d_in[6];
    const float* mam_cw   = (const float*)d_in[7];
    const float* mam_cb   = (const float*)d_in[8];
    const float* mam_dtb  = (const float*)d_in[9];
    const float* mam_Alog = (const float*)d_in[10];
    const float* mam_D    = (const float*)d_in[11];
    const float* mam_nw   = (const float*)d_in[12];
    const float* mam_ow   = (const float*)d_in[13];
    const float* fc_out_w = (const float*)d_in[14];
    const float* bn_g     = (const float*)d_in[15];
    const float* bn_b     = (const float*)d_in[16];
    const float* conv4_w  = (const float*)d_in[17];
    const float* conv4_b  = (const float*)d_in[18];
    float* out = (float*)d_out;

    cudaFuncSetAttribute(k_lin1,       cudaFuncAttributeMaxDynamicSharedMemorySize, 98304);
    cudaFuncSetAttribute(k_conv4,      cudaFuncAttributeMaxDynamicSharedMemorySize, 98304);
    cudaFuncSetAttribute(k_fcin,       cudaFuncAttributeMaxDynamicSharedMemorySize, 81920);
    cudaFuncSetAttribute(k_inproj,     cudaFuncAttributeMaxDynamicSharedMemorySize, 156352);
    cudaFuncSetAttribute(k_chunkstate, cudaFuncAttributeMaxDynamicSharedMemorySize, 67072);
    cudaFuncSetAttribute(k_output,     cudaFuncAttributeMaxDynamicSharedMemorySize, 156672);
    cudaFuncSetAttribute(k_outfuse,    cudaFuncAttributeMaxDynamicSharedMemorySize, 133120);

    k_lin1<<<dim3(32,2,BB), 256, 98304>>>(x, lin1_w, lin1_b);
    k_dw<<<BB*CC*HWD/256, 256>>>(dw_w, dw_b);
    k_fcin<<<dim3(32,BB), 256, 81920>>>(fc_in_w);
    k_inproj<<<dim3(BL/128, 2), 512, 156352>>>(mam_in_w, mam_cw, mam_cb, mam_dtb);
    k_chunkstate<<<dim3(NCHK, BB, 2), 256, 67072>>>(mam_Alog);
    k_chunkscan<<<dim3(BB, 2, 16), 256>>>(mam_Alog);
    k_output<<<dim3(NCHK, BB, 2), 256, 156672>>>(mam_Alog, mam_D, mam_nw);
    k_prepW<<<128, 128>>>(mam_ow, fc_out_w);
    k_outfuse<<<BL/128, 256, 133120>>>();
    k_bnstats<<<CC, 256>>>(bn_g, bn_b);
    k_prep4<<<1, CC>>>(conv4_w, conv4_b);
    k_conv4<<<dim3(32,2,BB), 256, 98304>>>(x, out);
}